// round 6
// baseline (speedup 1.0000x reference)
#include <cuda_runtime.h>

// GridToGraphConverter: B=4, C=16, H=W=512
//  out layout (float32, concatenated):
//   [0, NF)            node_features  (B*HW, C)
//   [NF, NF+E)         edge_index src row
//   [NF+E, NF+2E)      edge_index dst row
//   [NF+2E, NF+2E+2E)  edge_attr (E, 2)
// edge_index / edge offsets generated analytically (grid-8 structure).
//
// Parallelization: quad of 4 threads shares a 4-node group; each quad thread
// accumulates 4 of the 16 channels (x4 batches = 16 plane-iterations of
// 3x float4 LDG), shfl_xor butterfly sums the quad, per-slot sums are parked
// in smem, and the block then emits its CONTIGUOUS edge range coalesced via
// an inverse edge->(col,slot) map.

#define Wd 512
#define Hd 512
#define HWd (Wd * Hd)
#define Cc 16
#define Bb 4
#define NFSZ (Bb * HWd * Cc)        // 16777216
#define Ed 2091012
#define SS 260                       // smem stride (256-node tile + pad)

__global__ __launch_bounds__(256, 4) void g2g_kernel(const float* __restrict__ grid,
                                                     float* __restrict__ out) {
    __shared__ float sm[Cc * SS];    // transpose staging [c][node_in_half_row]
    __shared__ float sm_a[8 * SS];   // per-slot feature-diff sums [slot][col]

    const int tid = threadIdx.x;
    const int h = blockIdx.x >> 1;          // row
    const int half = blockIdx.x & 1;        // half-row
    const int q = tid & 3;                  // channel quad id
    const int lane = tid & 31;
    const int wg = half * 256 + (tid & ~3); // first column of 4-node group
    const int n0 = h * Wd + wg;             // first node of group

    const bool hasUp = (h > 0);
    const bool hasDn = (h < Hd - 1);
    const bool hasL = (wg > 0);
    const bool hasR = (wg < Wd - 4);

    const int oUp = hasUp ? n0 - Wd : n0;
    const int oDn = hasDn ? n0 + Wd : n0;
    // clamped fallback offsets for warp-edge lanes (values unused if invalid)
    const int oLm = hasL ? n0 - 1 : n0;
    const int oLu = hasL ? oUp - 1 : oUp;
    const int oLd = hasL ? oDn - 1 : oDn;
    const int oRm = hasR ? n0 + 4 : n0;
    const int oRu = hasR ? oUp + 4 : oUp;
    const int oRd = hasR ? oDn + 4 : oDn;

    float acc[4][8];
#pragma unroll
    for (int i = 0; i < 4; i++)
#pragma unroll
        for (int k = 0; k < 8; k++) acc[i][k] = 0.0f;

    for (int b = 0; b < Bb; b++) {
        const float* pb = grid + (size_t)b * (Cc * HWd);
#pragma unroll
        for (int ci = 0; ci < 4; ci++) {
            const int c = q * 4 + ci;           // this thread's channel
            const float* p = pb + c * HWd;
            float4 ow = *(const float4*)(p + n0);
            float4 up = *(const float4*)(p + oUp);
            float4 dn = *(const float4*)(p + oDn);
            *(float4*)&sm[c * SS + (tid & ~3)] = ow;   // stash for transpose

            // halo via intra-warp shuffles (quad-stride 4 = same channel,
            // adjacent node group); warp-edge lanes fall back to LDG.
            float mL = __shfl_up_sync(0xffffffffu, ow.w, 4);
            float uL = __shfl_up_sync(0xffffffffu, up.w, 4);
            float dL = __shfl_up_sync(0xffffffffu, dn.w, 4);
            float mR = __shfl_down_sync(0xffffffffu, ow.x, 4);
            float uR = __shfl_down_sync(0xffffffffu, up.x, 4);
            float dR = __shfl_down_sync(0xffffffffu, dn.x, 4);
            if (lane < 4) {
                mL = p[oLm];
                uL = p[oLu];
                dL = p[oLd];
            }
            if (lane >= 28) {
                mR = p[oRm];
                uR = p[oRu];
                dR = p[oRd];
            }

            float u[6] = {uL, up.x, up.y, up.z, up.w, uR};
            float m[6] = {mL, ow.x, ow.y, ow.z, ow.w, mR};
            float d[6] = {dL, dn.x, dn.y, dn.z, dn.w, dR};
#pragma unroll
            for (int i = 0; i < 4; i++) {
                float o = m[i + 1];
                acc[i][0] += fabsf(o - u[i]);
                acc[i][1] += fabsf(o - u[i + 1]);
                acc[i][2] += fabsf(o - u[i + 2]);
                acc[i][3] += fabsf(o - m[i]);
                acc[i][4] += fabsf(o - m[i + 2]);
                acc[i][5] += fabsf(o - d[i]);
                acc[i][6] += fabsf(o - d[i + 1]);
                acc[i][7] += fabsf(o - d[i + 2]);
            }
        }
        __syncthreads();
        // Coalesced node_features write: 256 nodes * 16 channels contiguous.
        float* dst = out + (size_t)b * HWd * Cc
                         + ((size_t)h * Wd + half * 256) * Cc;
#pragma unroll
        for (int j = 0; j < 4; j++) {
            int f = (tid + j * 256) * 4;    // flat float index in tile
            int nn = f >> 4;                // local node
            int c = f & 15;                 // channel (multiple of 4)
            float4 v;
            v.x = sm[(c + 0) * SS + nn];
            v.y = sm[(c + 1) * SS + nn];
            v.z = sm[(c + 2) * SS + nn];
            v.w = sm[(c + 3) * SS + nn];
            __stcs((float4*)(dst + f), v);  // streaming: don't pollute L2
        }
        __syncthreads();
    }

    // ---- Quad butterfly reduce: every lane gets full 64-plane sums ----
#pragma unroll
    for (int i = 0; i < 4; i++)
#pragma unroll
        for (int k = 0; k < 8; k++) {
            acc[i][k] += __shfl_xor_sync(0xffffffffu, acc[i][k], 1);
            acc[i][k] += __shfl_xor_sync(0xffffffffu, acc[i][k], 2);
        }

    // This thread owns node col = half*256 + tid; select its acc set (i == q)
    // and park the 8 per-slot sums in smem for the coalesced emitter.
    const float inv64 = 1.0f / 64.0f;
#pragma unroll
    for (int k = 0; k < 8; k++) {
        float v01 = (q & 1) ? acc[1][k] : acc[0][k];
        float v23 = (q & 1) ? acc[3][k] : acc[2][k];
        float a = (q & 2) ? v23 : v01;
        sm_a[k * SS + tid] = a * inv64;
    }
    __syncthreads();

    // ---- Coalesced edge emission over this block's contiguous e-range ----
    // boundary rows: 5W-4=2556 edges (1278/half); interior: 8W-6=4090 (2045/half)
    const bool boundaryRow = (h == 0) || (h == Hd - 1);
    const int rowBase = (h == 0) ? 0 : 2556 + (h - 1) * 4090;
    const int cnt = boundaryRow ? 1278 : 2045;
    const int eBase = rowBase + half * cnt;
    const int iters = boundaryRow ? 5 : 8;

    const float SQ2 = 1.41421356237309515f;
    float* eiS = out + NFSZ;
    float* eiD = out + NFSZ + Ed;
    float* ea  = out + NFSZ + 2 * Ed;

    for (int it = 0; it < iters; it++) {
        int le = it * 256 + tid;
        if (le >= cnt) break;
        int col_l, slot;
        if (!boundaryRow) {
            if (half == 0) {
                if (le < 5) { // col 0 valid slots {1,2,4,6,7}
                    col_l = 0;
                    slot = (le == 0) ? 1 : (le == 1) ? 2 : (le == 2) ? 4
                                      : (le == 3) ? 6 : 7;
                } else {
                    int j = le - 5;
                    col_l = 1 + (j >> 3);
                    slot = j & 7;
                }
            } else {
                if (le < 2040) {
                    col_l = le >> 3;
                    slot = le & 7;
                } else { // col 511 valid slots {0,1,3,5,6}
                    col_l = 255;
                    int r = le - 2040;
                    slot = (r == 0) ? 0 : (r == 1) ? 1 : (r == 2) ? 3
                                     : (r == 3) ? 5 : 6;
                }
            }
        } else if (h == 0) { // slots 3..7 only
            if (half == 0) {
                if (le < 3) { // col 0: {4,6,7}
                    col_l = 0;
                    slot = (le == 0) ? 4 : (le == 1) ? 6 : 7;
                } else {
                    int j = le - 3;
                    col_l = 1 + j / 5;
                    slot = 3 + (j - (j / 5) * 5);
                }
            } else {
                if (le < 1275) {
                    col_l = le / 5;
                    slot = 3 + (le - col_l * 5);
                } else { // col 511: {3,5,6}
                    col_l = 255;
                    int r = le - 1275;
                    slot = (r == 0) ? 3 : (r == 1) ? 5 : 6;
                }
            }
        } else { // h == 511: slots 0..4 only
            if (half == 0) {
                if (le < 3) { // col 0: {1,2,4}
                    col_l = 0;
                    slot = (le == 0) ? 1 : (le == 1) ? 2 : 4;
                } else {
                    int j = le - 3;
                    col_l = 1 + j / 5;
                    slot = j - (j / 5) * 5;
                }
            } else {
                if (le < 1275) {
                    col_l = le / 5;
                    slot = le - col_l * 5;
                } else { // col 511: {0,1,3}
                    col_l = 255;
                    int r = le - 1275;
                    slot = (r == 0) ? 0 : (r == 1) ? 1 : 3;
                }
            }
        }
        // slot -> (dh, dw), dist
        int dh = (slot < 3) ? -1 : ((slot >= 5) ? 1 : 0);
        int dw = ((0x42 >> slot) & 1) ? 0 : (((0x29 >> slot) & 1) ? -1 : 1);
        float ds = ((0xA5 >> slot) & 1) ? SQ2 : 1.0f;

        int col = half * 256 + col_l;
        int nn = h * Wd + col;
        int e = eBase + le;
        __stcs(eiS + e, (float)nn);
        __stcs(eiD + e, (float)(nn + dh * Wd + dw));
        __stcs((float2*)(ea + 2 * e), make_float2(ds, sm_a[slot * SS + col_l]));
    }
}

extern "C" void kernel_launch(void* const* d_in, const int* in_sizes, int n_in,
                              void* d_out, int out_size) {
    const float* grid = (const float*)d_in[0];
    float* out = (float*)d_out;
    // 1024 blocks x 256 threads: each block = half a grid row
    g2g_kernel<<<1024, 256>>>(grid, out);
}

// round 7
// speedup vs baseline: 1.6149x; 1.6149x over previous
#include <cuda_runtime.h>

// GridToGraphConverter: B=4, C=16, H=W=512
//  out layout (float32, concatenated):
//   [0, NF)            node_features  (B*HW, C)
//   [NF, NF+E)         edge_index src row
//   [NF+E, NF+2E)      edge_index dst row
//   [NF+2E, NF+2E+2E)  edge_attr (E, 2)
// edge_index / edge offsets generated analytically (grid-8 structure).
//
// Quad of 4 threads shares a 4-node group; each quad thread accumulates 4 of
// the 16 channels (x4 batches = 16 plane-iterations of 3x float4 LDG),
// shfl_xor butterfly sums the quad. Interior rows then park per-slot sums in
// smem and emit their CONTIGUOUS edge range fully coalesced (8 unrolled
// iterations, shift-LUT fixups, no divisions). Boundary rows (2 of 512) use
// the scattered per-node emitter.

#define Wd 512
#define Hd 512
#define HWd (Wd * Hd)
#define Cc 16
#define Bb 4
#define NFSZ (Bb * HWd * Cc)        // 16777216
#define Ed 2091012
#define SS 260                       // smem stride (256-node tile + pad)

__global__ __launch_bounds__(256, 4) void g2g_kernel(const float* __restrict__ grid,
                                                     float* __restrict__ out) {
    __shared__ float sm[Cc * SS];    // transpose staging / edge-sum park

    const int tid = threadIdx.x;
    const int h = blockIdx.x >> 1;          // row
    const int half = blockIdx.x & 1;        // half-row
    const int q = tid & 3;                  // channel quad id
    const int lane = tid & 31;
    const int wg = half * 256 + (tid & ~3); // first column of 4-node group
    const int n0 = h * Wd + wg;             // first node of group

    const bool hasUp = (h > 0);
    const bool hasDn = (h < Hd - 1);
    const bool hasL = (wg > 0);
    const bool hasR = (wg < Wd - 4);

    const int oUp = hasUp ? n0 - Wd : n0;
    const int oDn = hasDn ? n0 + Wd : n0;
    // clamped fallback offsets for warp-edge lanes (values unused if invalid)
    const int oLm = hasL ? n0 - 1 : n0;
    const int oLu = hasL ? oUp - 1 : oUp;
    const int oLd = hasL ? oDn - 1 : oDn;
    const int oRm = hasR ? n0 + 4 : n0;
    const int oRu = hasR ? oUp + 4 : oUp;
    const int oRd = hasR ? oDn + 4 : oDn;

    float acc[4][8];
#pragma unroll
    for (int i = 0; i < 4; i++)
#pragma unroll
        for (int k = 0; k < 8; k++) acc[i][k] = 0.0f;

    for (int b = 0; b < Bb; b++) {
        const float* pb = grid + (size_t)b * (Cc * HWd);
#pragma unroll
        for (int ci = 0; ci < 4; ci++) {
            const int c = q * 4 + ci;           // this thread's channel
            const float* p = pb + c * HWd;
            float4 ow = *(const float4*)(p + n0);
            float4 up = *(const float4*)(p + oUp);
            float4 dn = *(const float4*)(p + oDn);
            *(float4*)&sm[c * SS + (tid & ~3)] = ow;   // stash for transpose

            // halo via intra-warp shuffles (quad-stride 4 = same channel,
            // adjacent node group); warp-edge lanes fall back to LDG.
            float mL = __shfl_up_sync(0xffffffffu, ow.w, 4);
            float uL = __shfl_up_sync(0xffffffffu, up.w, 4);
            float dL = __shfl_up_sync(0xffffffffu, dn.w, 4);
            float mR = __shfl_down_sync(0xffffffffu, ow.x, 4);
            float uR = __shfl_down_sync(0xffffffffu, up.x, 4);
            float dR = __shfl_down_sync(0xffffffffu, dn.x, 4);
            if (lane < 4) {
                mL = p[oLm];
                uL = p[oLu];
                dL = p[oLd];
            }
            if (lane >= 28) {
                mR = p[oRm];
                uR = p[oRu];
                dR = p[oRd];
            }

            float u[6] = {uL, up.x, up.y, up.z, up.w, uR};
            float m[6] = {mL, ow.x, ow.y, ow.z, ow.w, mR};
            float d[6] = {dL, dn.x, dn.y, dn.z, dn.w, dR};
#pragma unroll
            for (int i = 0; i < 4; i++) {
                float o = m[i + 1];
                acc[i][0] += fabsf(o - u[i]);
                acc[i][1] += fabsf(o - u[i + 1]);
                acc[i][2] += fabsf(o - u[i + 2]);
                acc[i][3] += fabsf(o - m[i]);
                acc[i][4] += fabsf(o - m[i + 2]);
                acc[i][5] += fabsf(o - d[i]);
                acc[i][6] += fabsf(o - d[i + 1]);
                acc[i][7] += fabsf(o - d[i + 2]);
            }
        }
        __syncthreads();
        // Coalesced node_features write: 256 nodes * 16 channels contiguous.
        float* dst = out + (size_t)b * HWd * Cc
                         + ((size_t)h * Wd + half * 256) * Cc;
#pragma unroll
        for (int j = 0; j < 4; j++) {
            int f = (tid + j * 256) * 4;    // flat float index in tile
            int nn = f >> 4;                // local node
            int c = f & 15;                 // channel (multiple of 4)
            float4 v;
            v.x = sm[(c + 0) * SS + nn];
            v.y = sm[(c + 1) * SS + nn];
            v.z = sm[(c + 2) * SS + nn];
            v.w = sm[(c + 3) * SS + nn];
            *(float4*)(dst + f) = v;
        }
        __syncthreads();
    }

    // ---- Quad butterfly reduce: every lane gets full 64-plane sums ----
#pragma unroll
    for (int i = 0; i < 4; i++)
#pragma unroll
        for (int k = 0; k < 8; k++) {
            acc[i][k] += __shfl_xor_sync(0xffffffffu, acc[i][k], 1);
            acc[i][k] += __shfl_xor_sync(0xffffffffu, acc[i][k], 2);
        }

    // This thread owns node col = half*256 + tid; select its acc set (i == q).
    const float inv64 = 1.0f / 64.0f;
    float a[8];
#pragma unroll
    for (int k = 0; k < 8; k++) {
        float v01 = (q & 1) ? acc[1][k] : acc[0][k];
        float v23 = (q & 1) ? acc[3][k] : acc[2][k];
        a[k] = ((q & 2) ? v23 : v01) * inv64;
    }

    const float SQ2 = 1.41421356237309515f;
    float* eiS = out + NFSZ;
    float* eiD = out + NFSZ + Ed;
    float* ea  = out + NFSZ + 2 * Ed;
    const bool boundaryRow = (h == 0) || (h == Hd - 1);

    if (!boundaryRow) {
        // Park per-slot sums: sm[slot][col_l] (conflict-free both ways).
#pragma unroll
        for (int k = 0; k < 8; k++) sm[k * SS + tid] = a[k];
        __syncthreads();

        // Coalesced emission over this half-row's contiguous 2045 edges.
        const int eBase = 2556 + (h - 1) * 4090 + half * 2045;
#pragma unroll
        for (int it = 0; it < 8; it++) {
            int le = it * 256 + tid;
            if (le < 2045) {
                int col_l, slot;
                if (half == 0) {
                    if (le < 5) {               // col 0: slots {1,2,4,6,7}
                        col_l = 0;
                        slot = (0x76421 >> (4 * le)) & 0xF;
                    } else {
                        int j = le - 5;
                        col_l = 1 + (j >> 3);
                        slot = j & 7;
                    }
                } else {
                    if (le < 2040) {
                        col_l = le >> 3;
                        slot = le & 7;
                    } else {                    // col 511: slots {0,1,3,5,6}
                        col_l = 255;
                        slot = (0x65310 >> (4 * (le - 2040))) & 0xF;
                    }
                }
                int dh = (slot < 3) ? -1 : ((slot >= 5) ? 1 : 0);
                int dw = ((0x42 >> slot) & 1) ? 0
                         : (((0x29 >> slot) & 1) ? -1 : 1);
                float ds = ((0xA5 >> slot) & 1) ? SQ2 : 1.0f;

                int nn = h * Wd + half * 256 + col_l;
                int e = eBase + le;
                eiS[e] = (float)nn;
                eiD[e] = (float)(nn + dh * Wd + dw);
                *(float2*)(ea + 2 * e) = make_float2(ds, sm[slot * SS + col_l]);
            }
        }
    } else {
        // Boundary rows (h = 0 or 511): scattered per-node emission (2 rows).
        const int col = half * 256 + tid;
        const int dnk[8] = {-513, -512, -511, -1, 1, 511, 512, 513};
        const float dist[8] = {SQ2, 1.0f, SQ2, 1.0f, 1.0f, SQ2, 1.0f, SQ2};
        const int rowBase = (h == 0) ? 0 : 2556 + (h - 1) * 4090;
        int e = rowBase + ((col == 0) ? 0 : 3 + (col - 1) * 5);

        const int n = h * Wd + col;
        const bool vL = (col > 0);
        const bool vR = (col < Wd - 1);
        bool val[8] = {hasUp && vL, hasUp, hasUp && vR,
                       vL, vR,
                       hasDn && vL, hasDn, hasDn && vR};
#pragma unroll
        for (int k = 0; k < 8; k++) {
            if (val[k]) {
                eiS[e] = (float)n;
                eiD[e] = (float)(n + dnk[k]);
                ea[2 * e]     = dist[k];
                ea[2 * e + 1] = a[k];
                e++;
            }
        }
    }
}

extern "C" void kernel_launch(void* const* d_in, const int* in_sizes, int n_in,
                              void* d_out, int out_size) {
    const float* grid = (const float*)d_in[0];
    float* out = (float*)d_out;
    // 1024 blocks x 256 threads: each block = half a grid row
    g2g_kernel<<<1024, 256>>>(grid, out);
}

// round 8
// speedup vs baseline: 1.8786x; 1.1633x over previous
#include <cuda_runtime.h>

// GridToGraphConverter: B=4, C=16, H=W=512
//  out layout (float32, concatenated):
//   [0, NF)            node_features  (B*HW, C)
//   [NF, NF+E)         edge_index src row
//   [NF+E, NF+2E)      edge_index dst row
//   [NF+2E, NF+2E+2E)  edge_attr (E, 2)
// edge_index / edge offsets generated analytically (grid-8 structure).
//
// Quad of 4 threads shares a 4-node group; each quad thread accumulates 4 of
// the 16 channels (x4 batches = 16 plane-iterations of 3x float4 LDG),
// collects its channel-quad of node_features in registers and stores them
// directly (no smem transpose round-trip). shfl_xor butterfly sums the quad;
// interior rows emit their CONTIGUOUS edge range coalesced via smem park.

#define Wd 512
#define Hd 512
#define HWd (Wd * Hd)
#define Cc 16
#define Bb 4
#define NFSZ (Bb * HWd * Cc)        // 16777216
#define Ed 2091012
#define SS 260                       // smem stride (256 cols + pad)

__global__ __launch_bounds__(256, 3) void g2g_kernel(const float* __restrict__ grid,
                                                     float* __restrict__ out) {
    __shared__ float sm[8 * SS];     // per-slot feature-diff park [slot][col]

    const int tid = threadIdx.x;
    const int h = blockIdx.x >> 1;          // row
    const int half = blockIdx.x & 1;        // half-row
    const int q = tid & 3;                  // channel quad id
    const int lane = tid & 31;
    const int wg = half * 256 + (tid & ~3); // first column of 4-node group
    const int n0 = h * Wd + wg;             // first node of group

    const bool hasUp = (h > 0);
    const bool hasDn = (h < Hd - 1);
    const bool hasL = (wg > 0);
    const bool hasR = (wg < Wd - 4);

    const int oUp = hasUp ? n0 - Wd : n0;
    const int oDn = hasDn ? n0 + Wd : n0;
    // clamped fallback offsets for warp-edge lanes (values unused if invalid)
    const int oLm = hasL ? n0 - 1 : n0;
    const int oLu = hasL ? oUp - 1 : oUp;
    const int oLd = hasL ? oDn - 1 : oDn;
    const int oRm = hasR ? n0 + 4 : n0;
    const int oRu = hasR ? oUp + 4 : oUp;
    const int oRd = hasR ? oDn + 4 : oDn;

    float acc[4][8];
#pragma unroll
    for (int i = 0; i < 4; i++)
#pragma unroll
        for (int k = 0; k < 8; k++) acc[i][k] = 0.0f;

    for (int b = 0; b < Bb; b++) {
        const float* pb = grid + (size_t)b * (Cc * HWd);
        float nf[4][4];              // [node i][ci] channel-quad collection
#pragma unroll
        for (int ci = 0; ci < 4; ci++) {
            const int c = q * 4 + ci;           // this thread's channel
            const float* p = pb + c * HWd;
            float4 ow = *(const float4*)(p + n0);
            float4 up = *(const float4*)(p + oUp);
            float4 dn = *(const float4*)(p + oDn);
            nf[0][ci] = ow.x;
            nf[1][ci] = ow.y;
            nf[2][ci] = ow.z;
            nf[3][ci] = ow.w;

            // halo via intra-warp shuffles (quad-stride 4 = same channel,
            // adjacent node group); warp-edge lanes fall back to LDG.
            float mL = __shfl_up_sync(0xffffffffu, ow.w, 4);
            float uL = __shfl_up_sync(0xffffffffu, up.w, 4);
            float dL = __shfl_up_sync(0xffffffffu, dn.w, 4);
            float mR = __shfl_down_sync(0xffffffffu, ow.x, 4);
            float uR = __shfl_down_sync(0xffffffffu, up.x, 4);
            float dR = __shfl_down_sync(0xffffffffu, dn.x, 4);
            if (lane < 4) {
                mL = p[oLm];
                uL = p[oLu];
                dL = p[oLd];
            }
            if (lane >= 28) {
                mR = p[oRm];
                uR = p[oRu];
                dR = p[oRd];
            }

            float u[6] = {uL, up.x, up.y, up.z, up.w, uR};
            float m[6] = {mL, ow.x, ow.y, ow.z, ow.w, mR};
            float d[6] = {dL, dn.x, dn.y, dn.z, dn.w, dR};
#pragma unroll
            for (int i = 0; i < 4; i++) {
                float o = m[i + 1];
                acc[i][0] += fabsf(o - u[i]);
                acc[i][1] += fabsf(o - u[i + 1]);
                acc[i][2] += fabsf(o - u[i + 2]);
                acc[i][3] += fabsf(o - m[i]);
                acc[i][4] += fabsf(o - m[i + 2]);
                acc[i][5] += fabsf(o - d[i]);
                acc[i][6] += fabsf(o - d[i + 1]);
                acc[i][7] += fabsf(o - d[i + 2]);
            }
        }
        // Direct node_features store: node (n0+i), channels 4q..4q+3.
        float* dstb = out + (size_t)b * (HWd * Cc);
#pragma unroll
        for (int i = 0; i < 4; i++) {
            *(float4*)(dstb + (size_t)(n0 + i) * Cc + 4 * q) =
                make_float4(nf[i][0], nf[i][1], nf[i][2], nf[i][3]);
        }
    }

    // ---- Quad butterfly reduce: every lane gets full 64-plane sums ----
#pragma unroll
    for (int i = 0; i < 4; i++)
#pragma unroll
        for (int k = 0; k < 8; k++) {
            acc[i][k] += __shfl_xor_sync(0xffffffffu, acc[i][k], 1);
            acc[i][k] += __shfl_xor_sync(0xffffffffu, acc[i][k], 2);
        }

    // This thread owns node col = half*256 + tid; select its acc set (i == q).
    const float inv64 = 1.0f / 64.0f;
    float a[8];
#pragma unroll
    for (int k = 0; k < 8; k++) {
        float v01 = (q & 1) ? acc[1][k] : acc[0][k];
        float v23 = (q & 1) ? acc[3][k] : acc[2][k];
        a[k] = ((q & 2) ? v23 : v01) * inv64;
    }

    const float SQ2 = 1.41421356237309515f;
    float* eiS = out + NFSZ;
    float* eiD = out + NFSZ + Ed;
    float* ea  = out + NFSZ + 2 * Ed;
    const bool boundaryRow = (h == 0) || (h == Hd - 1);

    if (!boundaryRow) {
        // Park per-slot sums: sm[slot][col_l] (conflict-free both ways).
#pragma unroll
        for (int k = 0; k < 8; k++) sm[k * SS + tid] = a[k];
        __syncthreads();

        // Coalesced emission over this half-row's contiguous 2045 edges.
        const int eBase = 2556 + (h - 1) * 4090 + half * 2045;
#pragma unroll
        for (int it = 0; it < 8; it++) {
            int le = it * 256 + tid;
            if (le < 2045) {
                int col_l, slot;
                if (half == 0) {
                    if (le < 5) {               // col 0: slots {1,2,4,6,7}
                        col_l = 0;
                        slot = (0x76421 >> (4 * le)) & 0xF;
                    } else {
                        int j = le - 5;
                        col_l = 1 + (j >> 3);
                        slot = j & 7;
                    }
                } else {
                    if (le < 2040) {
                        col_l = le >> 3;
                        slot = le & 7;
                    } else {                    // col 511: slots {0,1,3,5,6}
                        col_l = 255;
                        slot = (0x65310 >> (4 * (le - 2040))) & 0xF;
                    }
                }
                int dh = (slot < 3) ? -1 : ((slot >= 5) ? 1 : 0);
                int dw = ((0x42 >> slot) & 1) ? 0
                         : (((0x29 >> slot) & 1) ? -1 : 1);
                float ds = ((0xA5 >> slot) & 1) ? SQ2 : 1.0f;

                int nn = h * Wd + half * 256 + col_l;
                int e = eBase + le;
                eiS[e] = (float)nn;
                eiD[e] = (float)(nn + dh * Wd + dw);
                *(float2*)(ea + 2 * e) = make_float2(ds, sm[slot * SS + col_l]);
            }
        }
    } else {
        // Boundary rows (h = 0 or 511): scattered per-node emission (2 rows).
        const int col = half * 256 + tid;
        const int dnk[8] = {-513, -512, -511, -1, 1, 511, 512, 513};
        const float dist[8] = {SQ2, 1.0f, SQ2, 1.0f, 1.0f, SQ2, 1.0f, SQ2};
        const int rowBase = (h == 0) ? 0 : 2556 + (h - 1) * 4090;
        int e = rowBase + ((col == 0) ? 0 : 3 + (col - 1) * 5);

        const int n = h * Wd + col;
        const bool vL = (col > 0);
        const bool vR = (col < Wd - 1);
        bool val[8] = {hasUp && vL, hasUp, hasUp && vR,
                       vL, vR,
                       hasDn && vL, hasDn, hasDn && vR};
#pragma unroll
        for (int k = 0; k < 8; k++) {
            if (val[k]) {
                eiS[e] = (float)n;
                eiD[e] = (float)(n + dnk[k]);
                ea[2 * e]     = dist[k];
                ea[2 * e + 1] = a[k];
                e++;
            }
        }
    }
}

extern "C" void kernel_launch(void* const* d_in, const int* in_sizes, int n_in,
                              void* d_out, int out_size) {
    const float* grid = (const float*)d_in[0];
    float* out = (float*)d_out;
    // 1024 blocks x 256 threads: each block = half a grid row
    g2g_kernel<<<1024, 256>>>(grid, out);
}

// round 9
// speedup vs baseline: 2.0092x; 1.0696x over previous
#include <cuda_runtime.h>

// GridToGraphConverter: B=4, C=16, H=W=512
//  out layout (float32, concatenated):
//   [0, NF)            node_features  (B*HW, C)
//   [NF, NF+E)         edge_index src row
//   [NF+E, NF+2E)      edge_index dst row
//   [NF+2E, NF+2E+2E)  edge_attr (E, 2)
// edge_index / edge offsets generated analytically (grid-8 structure).
//
// Quad of 4 threads shares a 4-node group; each quad thread accumulates 4 of
// the 16 channels (x4 batches), collects node_features channel-quads in regs
// and stores directly. Halo via stride-4 shuffles with a SINGLE merged
// predicated fallback region for warp-edge lanes; quad reduction via a
// 3-shuffle selective exchange. Interior rows emit their contiguous edge
// range coalesced via smem park.

#define Wd 512
#define Hd 512
#define HWd (Wd * Hd)
#define Cc 16
#define Bb 4
#define NFSZ (Bb * HWd * Cc)        // 16777216
#define Ed 2091012
#define SS 260                       // smem stride (256 cols + pad)

__global__ __launch_bounds__(256, 3) void g2g_kernel(const float* __restrict__ grid,
                                                     float* __restrict__ out) {
    __shared__ float sm[8 * SS];     // per-slot feature-diff park [slot][col]

    const int tid = threadIdx.x;
    const int h = blockIdx.x >> 1;          // row
    const int half = blockIdx.x & 1;        // half-row
    const int q = tid & 3;                  // channel quad id
    const int lane = tid & 31;
    const int wg = half * 256 + (tid & ~3); // first column of 4-node group
    const int n0 = h * Wd + wg;             // first node of group

    const bool hasUp = (h > 0);
    const bool hasDn = (h < Hd - 1);
    const bool hasL = (wg > 0);
    const bool hasR = (wg < Wd - 4);

    const int oUp = hasUp ? n0 - Wd : n0;
    const int oDn = hasDn ? n0 + Wd : n0;

    // Merged warp-edge halo fallback addresses (clamped; garbage values land
    // in never-emitted slots). Lanes 0-3 use the LEFT set, 28-31 the RIGHT.
    const bool leftSide = (lane < 4);
    const int om = leftSide ? (hasL ? n0 - 1 : n0) : (hasR ? n0 + 4 : n0);
    const int ou = leftSide ? (hasL ? oUp - 1 : oUp) : (hasR ? oUp + 4 : oUp);
    const int od = leftSide ? (hasL ? oDn - 1 : oDn) : (hasR ? oDn + 4 : oDn);
    const bool edgeLane = (lane < 4) || (lane >= 28);

    float acc[4][8];
#pragma unroll
    for (int i = 0; i < 4; i++)
#pragma unroll
        for (int k = 0; k < 8; k++) acc[i][k] = 0.0f;

    for (int b = 0; b < Bb; b++) {
        const float* pb = grid + (size_t)b * (Cc * HWd);
        float nf[4][4];              // [node i][ci] channel-quad collection
#pragma unroll
        for (int ci = 0; ci < 4; ci++) {
            const int c = q * 4 + ci;           // this thread's channel
            const float* p = pb + c * HWd;
            float4 ow = *(const float4*)(p + n0);
            float4 up = *(const float4*)(p + oUp);
            float4 dn = *(const float4*)(p + oDn);
            nf[0][ci] = ow.x;
            nf[1][ci] = ow.y;
            nf[2][ci] = ow.z;
            nf[3][ci] = ow.w;

            // halo via intra-warp shuffles (quad-stride 4 = same channel,
            // adjacent node group); warp-edge lanes overwrite their broken
            // side from a single merged predicated load region.
            float mL = __shfl_up_sync(0xffffffffu, ow.w, 4);
            float uL = __shfl_up_sync(0xffffffffu, up.w, 4);
            float dL = __shfl_up_sync(0xffffffffu, dn.w, 4);
            float mR = __shfl_down_sync(0xffffffffu, ow.x, 4);
            float uR = __shfl_down_sync(0xffffffffu, up.x, 4);
            float dR = __shfl_down_sync(0xffffffffu, dn.x, 4);
            if (edgeLane) {
                float v0 = p[om];
                float v1 = p[ou];
                float v2 = p[od];
                if (leftSide) {
                    mL = v0; uL = v1; dL = v2;
                } else {
                    mR = v0; uR = v1; dR = v2;
                }
            }

            float u[6] = {uL, up.x, up.y, up.z, up.w, uR};
            float m[6] = {mL, ow.x, ow.y, ow.z, ow.w, mR};
            float d[6] = {dL, dn.x, dn.y, dn.z, dn.w, dR};
#pragma unroll
            for (int i = 0; i < 4; i++) {
                float o = m[i + 1];
                acc[i][0] += fabsf(o - u[i]);
                acc[i][1] += fabsf(o - u[i + 1]);
                acc[i][2] += fabsf(o - u[i + 2]);
                acc[i][3] += fabsf(o - m[i]);
                acc[i][4] += fabsf(o - m[i + 2]);
                acc[i][5] += fabsf(o - d[i]);
                acc[i][6] += fabsf(o - d[i + 1]);
                acc[i][7] += fabsf(o - d[i + 2]);
            }
        }
        // Direct node_features store: node (n0+i), channels 4q..4q+3.
        float* dstb = out + (size_t)b * (HWd * Cc);
#pragma unroll
        for (int i = 0; i < 4; i++) {
            *(float4*)(dstb + (size_t)(n0 + i) * Cc + 4 * q) =
                make_float4(nf[i][0], nf[i][1], nf[i][2], nf[i][3]);
        }
    }

    // ---- Selective quad reduce: lane ends with ONLY node q's 8 sums ----
    // round 1 (xor 1): keep nodes {q&1, (q&1)+2}; round 2 (xor 2): keep node q.
    const float inv64 = 1.0f / 64.0f;
    const int p1 = q & 1;
    float a[8];
#pragma unroll
    for (int k = 0; k < 8; k++) {
        float sA = p1 ? acc[0][k] : acc[1][k];      // send node (1-p1)
        float sB = p1 ? acc[2][k] : acc[3][k];      // send node (1-p1)+2
        float rA = __shfl_xor_sync(0xffffffffu, sA, 1);
        float rB = __shfl_xor_sync(0xffffffffu, sB, 1);
        float kA = (p1 ? acc[1][k] : acc[0][k]) + rA;   // node p1 pair-sum
        float kB = (p1 ? acc[3][k] : acc[2][k]) + rB;   // node p1+2 pair-sum
        float s2 = (q & 2) ? kA : kB;               // send what partner keeps
        float r2 = __shfl_xor_sync(0xffffffffu, s2, 2);
        a[k] = (((q & 2) ? kB : kA) + r2) * inv64;
    }

    const float SQ2 = 1.41421356237309515f;
    float* eiS = out + NFSZ;
    float* eiD = out + NFSZ + Ed;
    float* ea  = out + NFSZ + 2 * Ed;
    const bool boundaryRow = (h == 0) || (h == Hd - 1);

    if (!boundaryRow) {
        // Park per-slot sums: sm[slot][col_l] (conflict-free both ways).
#pragma unroll
        for (int k = 0; k < 8; k++) sm[k * SS + tid] = a[k];
        __syncthreads();

        // Coalesced emission over this half-row's contiguous 2045 edges.
        const int eBase = 2556 + (h - 1) * 4090 + half * 2045;
#pragma unroll
        for (int it = 0; it < 8; it++) {
            int le = it * 256 + tid;
            if (le < 2045) {
                int col_l, slot;
                if (half == 0) {
                    if (le < 5) {               // col 0: slots {1,2,4,6,7}
                        col_l = 0;
                        slot = (0x76421 >> (4 * le)) & 0xF;
                    } else {
                        int j = le - 5;
                        col_l = 1 + (j >> 3);
                        slot = j & 7;
                    }
                } else {
                    if (le < 2040) {
                        col_l = le >> 3;
                        slot = le & 7;
                    } else {                    // col 511: slots {0,1,3,5,6}
                        col_l = 255;
                        slot = (0x65310 >> (4 * (le - 2040))) & 0xF;
                    }
                }
                int dh = (slot < 3) ? -1 : ((slot >= 5) ? 1 : 0);
                int dw = ((0x42 >> slot) & 1) ? 0
                         : (((0x29 >> slot) & 1) ? -1 : 1);
                float ds = ((0xA5 >> slot) & 1) ? SQ2 : 1.0f;

                int nn = h * Wd + half * 256 + col_l;
                int e = eBase + le;
                eiS[e] = (float)nn;
                eiD[e] = (float)(nn + dh * Wd + dw);
                *(float2*)(ea + 2 * e) = make_float2(ds, sm[slot * SS + col_l]);
            }
        }
    } else {
        // Boundary rows (h = 0 or 511): scattered per-node emission (2 rows).
        const int col = half * 256 + tid;
        const int dnk[8] = {-513, -512, -511, -1, 1, 511, 512, 513};
        const float dist[8] = {SQ2, 1.0f, SQ2, 1.0f, 1.0f, SQ2, 1.0f, SQ2};
        const int rowBase = (h == 0) ? 0 : 2556 + (h - 1) * 4090;
        int e = rowBase + ((col == 0) ? 0 : 3 + (col - 1) * 5);

        const int n = h * Wd + col;
        const bool vL = (col > 0);
        const bool vR = (col < Wd - 1);
        bool val[8] = {hasUp && vL, hasUp, hasUp && vR,
                       vL, vR,
                       hasDn && vL, hasDn, hasDn && vR};
#pragma unroll
        for (int k = 0; k < 8; k++) {
            if (val[k]) {
                eiS[e] = (float)n;
                eiD[e] = (float)(n + dnk[k]);
                ea[2 * e]     = dist[k];
                ea[2 * e + 1] = a[k];
                e++;
            }
        }
    }
}

extern "C" void kernel_launch(void* const* d_in, const int* in_sizes, int n_in,
                              void* d_out, int out_size) {
    const float* grid = (const float*)d_in[0];
    float* out = (float*)d_out;
    // 1024 blocks x 256 threads: each block = half a grid row
    g2g_kernel<<<1024, 256>>>(grid, out);
}

// round 11
// speedup vs baseline: 2.1360x; 1.0631x over previous
#include <cuda_runtime.h>

// GridToGraphConverter: B=4, C=16, H=W=512
//  out layout (float32, concatenated):
//   [0, NF)            node_features  (B*HW, C)
//   [NF, NF+E)         edge_index src row
//   [NF+E, NF+2E)      edge_index dst row
//   [NF+2E, NF+2E+2E)  edge_attr (E, 2)
// edge_index / edge offsets generated analytically (grid-8 structure).
//
// Quad of 4 threads shares a 4-node group; each quad thread accumulates 4 of
// the 16 channels (x4 batches). Cross-group halo handled by the EXPORT
// scheme: per plane only mid-row neighbor values (mL/mR) are exchanged
// (2 shuffles); the 4 diagonal cross-boundary diffs are accumulated by the
// neighbor that owns the data and exchanged ONCE post-loop via smem (which
// also bridges warp boundaries, so warp-edge lanes load just 1 scalar/plane).
// Selective 3-shuffle quad reduce; interior rows emit their contiguous edge
// range coalesced via smem park.

#define Wd 512
#define Hd 512
#define HWd (Wd * Hd)
#define Cc 16
#define Bb 4
#define NFSZ (Bb * HWd * Cc)        // 16777216
#define Ed 2091012
#define SS 260                       // smem stride (256 cols + pad)

__global__ __launch_bounds__(256, 3) void g2g_kernel(const float* __restrict__ grid,
                                                     float* __restrict__ out) {
    __shared__ float4 sm_e[256];     // post-loop export exchange
    __shared__ float sm[8 * SS];     // per-slot feature-diff park [slot][col]

    const int tid = threadIdx.x;
    const int h = blockIdx.x >> 1;          // row
    const int half = blockIdx.x & 1;        // half-row
    const int q = tid & 3;                  // channel quad id
    const int lane = tid & 31;
    const int wg = half * 256 + (tid & ~3); // first column of 4-node group
    const int n0 = h * Wd + wg;             // first node of group

    const bool hasUp = (h > 0);
    const bool hasDn = (h < Hd - 1);
    const bool hasL = (wg > 0);
    const bool hasR = (wg < Wd - 4);

    const int oUp = hasUp ? n0 - Wd : n0;
    const int oDn = hasDn ? n0 + Wd : n0;

    // Warp-edge lanes: mid-row neighbor via 1 scalar load (clamped).
    const bool leftSide = (lane < 4);
    const bool edgeLane = (lane < 4) || (lane >= 28);
    const int oEm = leftSide ? (hasL ? n0 - 1 : n0) : (hasR ? n0 + 4 : n0);

    // Block-edge threads: diagonal halo via local loads (no smem exports
    // available from outside the block).
    const bool bEdgeL = (tid < 4);
    const bool bEdgeR = (tid >= 252);
    const int oEu = bEdgeL ? (hasL ? oUp - 1 : oUp) : (hasR ? oUp + 4 : oUp);
    const int oEd = bEdgeL ? (hasL ? oDn - 1 : oDn) : (hasR ? oDn + 4 : oDn);

    float acc[4][8];
#pragma unroll
    for (int i = 0; i < 4; i++)
#pragma unroll
        for (int k = 0; k < 8; k++) acc[i][k] = 0.0f;
    float e0 = 0.0f, e1 = 0.0f, e2 = 0.0f, e3 = 0.0f;   // exports

    for (int b = 0; b < Bb; b++) {
        const float* pb = grid + (size_t)b * (Cc * HWd);
        float nf[4][4];              // [node i][ci] channel-quad collection
#pragma unroll
        for (int ci = 0; ci < 4; ci++) {
            const int c = q * 4 + ci;           // this thread's channel
            const float* p = pb + c * HWd;
            float4 ow = *(const float4*)(p + n0);
            float4 up = *(const float4*)(p + oUp);
            float4 dn = *(const float4*)(p + oDn);
            nf[0][ci] = ow.x;
            nf[1][ci] = ow.y;
            nf[2][ci] = ow.z;
            nf[3][ci] = ow.w;

            // mid-row neighbor values (only cross-group data needed per plane)
            float mL = __shfl_up_sync(0xffffffffu, ow.w, 4);
            float mR = __shfl_down_sync(0xffffffffu, ow.x, 4);
            if (edgeLane) {
                float v = p[oEm];
                if (leftSide) mL = v; else mR = v;
            }
            if (bEdgeL) {       // local diagonal halo (left block edge)
                acc[0][0] += fabsf(ow.x - p[oEu]);
                acc[0][5] += fabsf(ow.x - p[oEd]);
            }
            if (bEdgeR) {       // local diagonal halo (right block edge)
                acc[3][2] += fabsf(ow.w - p[oEu]);
                acc[3][7] += fabsf(ow.w - p[oEd]);
            }

            // node 0 (slots 0,5 come from left neighbor's exports)
            acc[0][1] += fabsf(ow.x - up.x);
            acc[0][2] += fabsf(ow.x - up.y);
            acc[0][3] += fabsf(ow.x - mL);
            acc[0][4] += fabsf(ow.x - ow.y);
            acc[0][6] += fabsf(ow.x - dn.x);
            acc[0][7] += fabsf(ow.x - dn.y);
            // node 1 (all local)
            acc[1][0] += fabsf(ow.y - up.x);
            acc[1][1] += fabsf(ow.y - up.y);
            acc[1][2] += fabsf(ow.y - up.z);
            acc[1][3] += fabsf(ow.y - ow.x);
            acc[1][4] += fabsf(ow.y - ow.z);
            acc[1][5] += fabsf(ow.y - dn.x);
            acc[1][6] += fabsf(ow.y - dn.y);
            acc[1][7] += fabsf(ow.y - dn.z);
            // node 2 (all local)
            acc[2][0] += fabsf(ow.z - up.y);
            acc[2][1] += fabsf(ow.z - up.z);
            acc[2][2] += fabsf(ow.z - up.w);
            acc[2][3] += fabsf(ow.z - ow.y);
            acc[2][4] += fabsf(ow.z - ow.w);
            acc[2][5] += fabsf(ow.z - dn.y);
            acc[2][6] += fabsf(ow.z - dn.z);
            acc[2][7] += fabsf(ow.z - dn.w);
            // node 3 (slots 2,7 come from right neighbor's exports)
            acc[3][0] += fabsf(ow.w - up.z);
            acc[3][1] += fabsf(ow.w - up.w);
            acc[3][3] += fabsf(ow.w - ow.z);
            acc[3][4] += fabsf(ow.w - mR);
            acc[3][5] += fabsf(ow.w - dn.z);
            acc[3][6] += fabsf(ow.w - dn.w);
            // exports: diffs belonging to neighbors, computed with OUR rows
            e0 += fabsf(mL - up.x);   // left nb node3 slot2 (up-right)
            e1 += fabsf(mL - dn.x);   // left nb node3 slot7 (down-right)
            e2 += fabsf(mR - up.w);   // right nb node0 slot0 (up-left)
            e3 += fabsf(mR - dn.w);   // right nb node0 slot5 (down-left)
        }
        // Direct node_features store: node (n0+i), channels 4q..4q+3.
        float* dstb = out + (size_t)b * (HWd * Cc);
#pragma unroll
        for (int i = 0; i < 4; i++) {
            *(float4*)(dstb + (size_t)(n0 + i) * Cc + 4 * q) =
                make_float4(nf[i][0], nf[i][1], nf[i][2], nf[i][3]);
        }
    }

    // ---- Export exchange (bridges warp boundaries too) ----
    sm_e[tid] = make_float4(e0, e1, e2, e3);
    __syncthreads();
    if (!bEdgeL) {      // left neighbor's e2,e3 -> my node0 slots 0,5
        float4 v = sm_e[tid - 4];
        acc[0][0] = v.z;
        acc[0][5] = v.w;
    }
    if (!bEdgeR) {      // right neighbor's e0,e1 -> my node3 slots 2,7
        float4 v = sm_e[tid + 4];
        acc[3][2] = v.x;
        acc[3][7] = v.y;
    }

    // ---- Selective quad reduce: lane ends with ONLY node q's 8 sums ----
    const float inv64 = 1.0f / 64.0f;
    const int p1 = q & 1;
    float a[8];
#pragma unroll
    for (int k = 0; k < 8; k++) {
        float sA = p1 ? acc[0][k] : acc[1][k];      // send node (1-p1)
        float sB = p1 ? acc[2][k] : acc[3][k];      // send node (1-p1)+2
        float rA = __shfl_xor_sync(0xffffffffu, sA, 1);
        float rB = __shfl_xor_sync(0xffffffffu, sB, 1);
        float kA = (p1 ? acc[1][k] : acc[0][k]) + rA;   // node p1 pair-sum
        float kB = (p1 ? acc[3][k] : acc[2][k]) + rB;   // node p1+2 pair-sum
        float s2 = (q & 2) ? kA : kB;               // send what partner keeps
        float r2 = __shfl_xor_sync(0xffffffffu, s2, 2);
        a[k] = (((q & 2) ? kB : kA) + r2) * inv64;
    }

    const float SQ2 = 1.41421356237309515f;
    float* eiS = out + NFSZ;
    float* eiD = out + NFSZ + Ed;
    float* ea  = out + NFSZ + 2 * Ed;
    const bool boundaryRow = (h == 0) || (h == Hd - 1);

    if (!boundaryRow) {
        // Park per-slot sums: sm[slot][col_l] (conflict-free both ways).
#pragma unroll
        for (int k = 0; k < 8; k++) sm[k * SS + tid] = a[k];
        __syncthreads();

        // Coalesced emission over this half-row's contiguous 2045 edges.
        const int eBase = 2556 + (h - 1) * 4090 + half * 2045;
#pragma unroll
        for (int it = 0; it < 8; it++) {
            int le = it * 256 + tid;
            if (le < 2045) {
                int col_l, slot;
                if (half == 0) {
                    if (le < 5) {               // col 0: slots {1,2,4,6,7}
                        col_l = 0;
                        slot = (0x76421 >> (4 * le)) & 0xF;
                    } else {
                        int j = le - 5;
                        col_l = 1 + (j >> 3);
                        slot = j & 7;
                    }
                } else {
                    if (le < 2040) {
                        col_l = le >> 3;
                        slot = le & 7;
                    } else {                    // col 511: slots {0,1,3,5,6}
                        col_l = 255;
                        slot = (0x65310 >> (4 * (le - 2040))) & 0xF;
                    }
                }
                int dh = (slot < 3) ? -1 : ((slot >= 5) ? 1 : 0);
                int dw = ((0x42 >> slot) & 1) ? 0
                         : (((0x29 >> slot) & 1) ? -1 : 1);
                float ds = ((0xA5 >> slot) & 1) ? SQ2 : 1.0f;

                int nn = h * Wd + half * 256 + col_l;
                int e = eBase + le;
                eiS[e] = (float)nn;
                eiD[e] = (float)(nn + dh * Wd + dw);
                *(float2*)(ea + 2 * e) = make_float2(ds, sm[slot * SS + col_l]);
            }
        }
    } else {
        // Boundary rows (h = 0 or 511): scattered per-node emission (2 rows).
        const int col = half * 256 + tid;
        const int dnk[8] = {-513, -512, -511, -1, 1, 511, 512, 513};
        const float dist[8] = {SQ2, 1.0f, SQ2, 1.0f, 1.0f, SQ2, 1.0f, SQ2};
        const int rowBase = (h == 0) ? 0 : 2556 + (h - 1) * 4090;
        int e = rowBase + ((col == 0) ? 0 : 3 + (col - 1) * 5);

        const int n = h * Wd + col;
        const bool vL = (col > 0);
        const bool vR = (col < Wd - 1);
        bool val[8] = {hasUp && vL, hasUp, hasUp && vR,
                       vL, vR,
                       hasDn && vL, hasDn, hasDn && vR};
#pragma unroll
        for (int k = 0; k < 8; k++) {
            if (val[k]) {
                eiS[e] = (float)n;
                eiD[e] = (float)(n + dnk[k]);
                ea[2 * e]     = dist[k];
                ea[2 * e + 1] = a[k];
                e++;
            }
        }
    }
}

extern "C" void kernel_launch(void* const* d_in, const int* in_sizes, int n_in,
                              void* d_out, int out_size) {
    const float* grid = (const float*)d_in[0];
    float* out = (float*)d_out;
    // 1024 blocks x 256 threads: each block = half a grid row
    g2g_kernel<<<1024, 256>>>(grid, out);
}